// round 1
// baseline (speedup 1.0000x reference)
#include <cuda_runtime.h>

// ---------------------------------------------------------------------------
// Problem constants
// ---------------------------------------------------------------------------
// B=8, H=126, W=126, F=64, D=32; arrays padded to (8, 128, 128, 32)
// float4 layout over d: strides (in float4): d4:1, c:8, r:1024, b:131072
// Total float4 per field array: 8*128*128*8 = 1,048,576 (16 MB)

constexpr double dDX  = 2.0 / 9.0;     // 2/(B+1)
constexpr double dDY  = 2.0 / 127.0;   // 2/(H+1)
constexpr double dDX2 = dDX * dDX;
constexpr double dDY2 = dDY * dDY;
constexpr double dDEN = 2.0 * (dDX2 + dDY2);

#define F_DX2  ((float)dDX2)
#define F_DY2  ((float)dDY2)
#define F_IDEN ((float)(1.0 / dDEN))
#define F_CB   ((float)(dDX2 * dDY2 / dDEN))
#define F_I2DX ((float)(1.0 / (2.0 * dDX)))
#define F_I2DY ((float)(1.0 / (2.0 * dDY)))
#define F_IDT  (10.0f)                       // 1/DT
#define F_DTDX ((float)(0.1 / dDX))          // DT/DX
#define F_DTDY ((float)(0.1 / dDY))          // DT/DY
#define F_PGX  ((float)(0.1 / (2.0 * dDX)))  // DT/(2*RHO*DX)
#define F_PGY  ((float)(0.1 / (2.0 * dDY)))  // DT/(2*RHO*DY)
#define F_NUX  ((float)(0.01 / dDX2))        // NU*DT/DX2
#define F_NUY  ((float)(0.01 / dDY2))        // NU*DT/DY2
#define F_FDT  (0.1f)                        // FRC*DT

#define NQ4 (1 << 20)   // float4 elements per field array

// ---------------------------------------------------------------------------
// Device scratch (allocation-free: __device__ globals)
// ---------------------------------------------------------------------------
__device__ float4 g_pA[NQ4];
__device__ float4 g_pB[NQ4];
__device__ float4 g_bb[NQ4];
__device__ float4 g_uA[NQ4];
__device__ float4 g_uB[NQ4];
__device__ float4 g_vA[NQ4];
__device__ float4 g_vB[NQ4];

// ---------------------------------------------------------------------------
// Init kernel: p0[b,h,w,d] = sum_f xpad[b,h,w,f] * wmat[d,f] + b_lin[d]
// (border of padded x is zero -> border p0 = b_lin[d])
// Block: 256 threads computes 64 positions x 32 d. Grid: 2048 blocks (exact).
// ---------------------------------------------------------------------------
__global__ __launch_bounds__(256) void init_p(
    const float* __restrict__ x, const float* __restrict__ wmat,
    const float* __restrict__ b_lin, float4* __restrict__ p0)
{
    __shared__ float xs[64][65];   // [pos_local][f], padded to kill bank conflicts
    __shared__ float wt[64][32];   // [f][d] (transposed w)

    int tid = threadIdx.x;

    for (int i = tid; i < 64 * 32; i += 256) {
        int f = i >> 5, d = i & 31;
        wt[f][d] = wmat[d * 64 + f];
    }

    int posBase = blockIdx.x * 64;
    for (int i = tid; i < 64 * 64; i += 256) {
        int pl = i >> 6, f = i & 63;
        int pos = posBase + pl;          // 0..131071
        int b   = pos >> 14;
        int rc  = pos & 16383;
        int h   = rc >> 7, wc = rc & 127;
        float val = 0.0f;
        if (h >= 1 && h <= 126 && wc >= 1 && wc <= 126)
            val = x[((b * 126 + (h - 1)) * 126 + (wc - 1)) * 64 + f];
        xs[pl][f] = val;
    }
    __syncthreads();

    int d4 = tid & 7;
    int pp = tid >> 3;          // 0..31 -> positions 2*pp, 2*pp+1
    int pl0 = pp * 2, pl1 = pl0 + 1;

    float4 a0 = make_float4(0.f, 0.f, 0.f, 0.f);
    float4 a1 = make_float4(0.f, 0.f, 0.f, 0.f);
    const float4* wt4 = (const float4*)&wt[0][0];   // wt4[f*8 + d4]

#pragma unroll 16
    for (int f = 0; f < 64; f++) {
        float4 wv = wt4[f * 8 + d4];
        float xa = xs[pl0][f];
        float xb = xs[pl1][f];
        a0.x += xa * wv.x; a0.y += xa * wv.y; a0.z += xa * wv.z; a0.w += xa * wv.w;
        a1.x += xb * wv.x; a1.y += xb * wv.y; a1.z += xb * wv.z; a1.w += xb * wv.w;
    }

    float4 bl = ((const float4*)b_lin)[d4];
    a0.x += bl.x; a0.y += bl.y; a0.z += bl.z; a0.w += bl.w;
    a1.x += bl.x; a1.y += bl.y; a1.z += bl.z; a1.w += bl.w;

    int posA = posBase + pl0;
    p0[posA * 8 + d4]       = a0;
    p0[(posA + 1) * 8 + d4] = a1;
}

// ---------------------------------------------------------------------------
// build_b: b = (du_dx+dv_dy)/DT - du_dx^2 - 2*du_dy*dv_dx - dv_dy^2 (RHO=1)
// rows 1..126, all 128 cols (periodic). b rows 0/127 never read by Jacobi.
// Grid (16,32,8), block (64,4).
// ---------------------------------------------------------------------------
__global__ __launch_bounds__(256) void build_b_k(
    const float4* __restrict__ u, const float4* __restrict__ v,
    float4* __restrict__ bb)
{
    int d4 = threadIdx.x & 7;
    int c  = (blockIdx.x << 3) + (threadIdx.x >> 3);
    int r  = 1 + (blockIdx.y << 2) + threadIdx.y;
    int b  = blockIdx.z;
    if (r > 126) return;

    int cE = (c + 1) & 127, cW = (c - 1) & 127;
    int rowbase = (((b << 7) + r) << 10) + d4;
    int i0 = rowbase + (c << 3);
    int iE = rowbase + (cE << 3);
    int iW = rowbase + (cW << 3);

    float4 ue = u[iE], uw = u[iW], un_ = u[i0 - 1024], us = u[i0 + 1024];
    float4 ve = v[iE], vw = v[iW], vn_ = v[i0 - 1024], vs = v[i0 + 1024];
    float4 o;

#define BCOMP(q) { \
    float dudx = (ue.q - uw.q) * F_I2DX; \
    float dvdy = (vs.q - vn_.q) * F_I2DY; \
    float dudy = (us.q - un_.q) * F_I2DY; \
    float dvdx = (ve.q - vw.q) * F_I2DX; \
    o.q = (dudx + dvdy) * F_IDT - dudx * dudx - 2.0f * dudy * dvdx - dvdy * dvdy; }
    BCOMP(x) BCOMP(y) BCOMP(z) BCOMP(w)
#undef BCOMP

    bb[i0] = o;
}

// ---------------------------------------------------------------------------
// Jacobi pressure sweep: rows 1..126 all cols (periodic), then
// row0 := row1(new), row127 := row126(new).
// ---------------------------------------------------------------------------
__global__ __launch_bounds__(256) void jacobi_k(
    const float4* __restrict__ pin, const float4* __restrict__ bb,
    float4* __restrict__ pout)
{
    int d4 = threadIdx.x & 7;
    int c  = (blockIdx.x << 3) + (threadIdx.x >> 3);
    int r  = 1 + (blockIdx.y << 2) + threadIdx.y;
    int b  = blockIdx.z;
    if (r > 126) return;

    int cE = (c + 1) & 127, cW = (c - 1) & 127;
    int rowbase = (((b << 7) + r) << 10) + d4;
    int i0 = rowbase + (c << 3);

    float4 e = pin[rowbase + (cE << 3)];
    float4 w = pin[rowbase + (cW << 3)];
    float4 n = pin[i0 - 1024];
    float4 s = pin[i0 + 1024];
    float4 bv = bb[i0];
    float4 o;

#define JCOMP(q) o.q = ((e.q + w.q) * F_DY2 + (n.q + s.q) * F_DX2) * F_IDEN - F_CB * bv.q;
    JCOMP(x) JCOMP(y) JCOMP(z) JCOMP(w)
#undef JCOMP

    pout[i0] = o;
    if (r == 1)   pout[i0 - 1024] = o;
    if (r == 126) pout[i0 + 1024] = o;
}

// ---------------------------------------------------------------------------
// Velocity step: rows 1..126 all cols (periodic); rows 0/127 set to zero.
// ---------------------------------------------------------------------------
__global__ __launch_bounds__(256) void velocity_k(
    const float4* __restrict__ u, const float4* __restrict__ v,
    const float4* __restrict__ p,
    float4* __restrict__ uo, float4* __restrict__ vo)
{
    int d4 = threadIdx.x & 7;
    int c  = (blockIdx.x << 3) + (threadIdx.x >> 3);
    int r  = 1 + (blockIdx.y << 2) + threadIdx.y;
    int b  = blockIdx.z;
    if (r > 126) return;

    int cE = (c + 1) & 127, cW = (c - 1) & 127;
    int rowbase = (((b << 7) + r) << 10) + d4;
    int i0 = rowbase + (c << 3);
    int iE = rowbase + (cE << 3);
    int iW = rowbase + (cW << 3);

    float4 uC = u[i0], uE = u[iE], uW = u[iW], uN = u[i0 - 1024], uS = u[i0 + 1024];
    float4 vC = v[i0], vE = v[iE], vW = v[iW], vN = v[i0 - 1024], vS = v[i0 + 1024];
    float4 pE = p[iE], pW = p[iW], pN = p[i0 - 1024], pS = p[i0 + 1024];
    float4 ou, ov;

#define VCOMP(q) { \
    float uc = uC.q, vc = vC.q; \
    ou.q = uc - uc * F_DTDX * (uc - uW.q) - vc * F_DTDY * (uc - uN.q) \
         - F_PGX * (pE.q - pW.q) \
         + F_NUX * (uE.q - 2.0f * uc + uW.q) + F_NUY * (uS.q - 2.0f * uc + uN.q) \
         + F_FDT; \
    ov.q = vc - uc * F_DTDX * (vc - vW.q) - vc * F_DTDY * (vc - vN.q) \
         - F_PGY * (pS.q - pN.q) \
         + F_NUX * (vE.q - 2.0f * vc + vW.q) + F_NUY * (vS.q - 2.0f * vc + vN.q); }
    VCOMP(x) VCOMP(y) VCOMP(z) VCOMP(w)
#undef VCOMP

    uo[i0] = ou;
    vo[i0] = ov;
    float4 z = make_float4(0.f, 0.f, 0.f, 0.f);
    if (r == 1)   { uo[i0 - 1024] = z; vo[i0 - 1024] = z; }
    if (r == 126) { uo[i0 + 1024] = z; vo[i0 + 1024] = z; }
}

// ---------------------------------------------------------------------------
// Extract output: out[b, c, d] = p[b, 127, c, d]  (8*128*32 floats = 8192 f4)
// ---------------------------------------------------------------------------
__global__ __launch_bounds__(256) void extract_k(
    const float4* __restrict__ p, float4* __restrict__ out)
{
    int t = blockIdx.x * 256 + threadIdx.x;   // 0..8191
    int b = t >> 10;
    int rem = t & 1023;
    out[t] = p[(((b << 7) + 127) << 10) + rem];
}

// ---------------------------------------------------------------------------
// Host driver (graph-capturable: kernel launches only)
// ---------------------------------------------------------------------------
extern "C" void kernel_launch(void* const* d_in, const int* in_sizes, int n_in,
                              void* d_out, int out_size)
{
    const float* x    = (const float*)d_in[0];
    const float* u0   = (const float*)d_in[1];
    const float* v0   = (const float*)d_in[2];
    const float* wm   = (const float*)d_in[3];
    const float* blin = (const float*)d_in[4];

    float4 *pA, *pB, *bb, *uA, *uB, *vA, *vB;
    cudaGetSymbolAddress((void**)&pA, g_pA);
    cudaGetSymbolAddress((void**)&pB, g_pB);
    cudaGetSymbolAddress((void**)&bb, g_bb);
    cudaGetSymbolAddress((void**)&uA, g_uA);
    cudaGetSymbolAddress((void**)&uB, g_uB);
    cudaGetSymbolAddress((void**)&vA, g_vA);
    cudaGetSymbolAddress((void**)&vB, g_vB);

    dim3 grd(16, 32, 8);
    dim3 blk(64, 4);

    init_p<<<2048, 256>>>(x, wm, blin, pA);

    const float4* ucur = (const float4*)u0;
    const float4* vcur = (const float4*)v0;

    for (int it = 0; it < 3; ++it) {
        build_b_k<<<grd, blk>>>(ucur, vcur, bb);

        float4* pi = pA;
        float4* po = pB;
        for (int k = 0; k < 20; ++k) {
            jacobi_k<<<grd, blk>>>(pi, bb, po);
            float4* t = pi; pi = po; po = t;
        }
        // 20 sweeps (even) -> result back in pA

        if (it < 2) {
            float4* uo = (it == 0) ? uA : uB;
            float4* vo = (it == 0) ? vA : vB;
            velocity_k<<<grd, blk>>>(ucur, vcur, pA, uo, vo);
            ucur = uo;
            vcur = vo;
        }
        // it == 2: velocity result is dead (output only depends on p)
    }

    extract_k<<<32, 256>>>(pA, (float4*)d_out);
}

// round 2
// speedup vs baseline: 2.9883x; 2.9883x over previous
#include <cuda_runtime.h>

// ---------------------------------------------------------------------------
// Problem constants: B=8, H=126, W=126, F=64, D=32; grids padded to 128x128
// Internal layout is PLANE-MAJOR: field[(b*32+d)][r][c], plane = 16384 floats.
// All 256 (b,d) planes evolve independently after the init GEMM.
// ---------------------------------------------------------------------------
constexpr double dDX  = 2.0 / 9.0;     // 2/(B+1)
constexpr double dDY  = 2.0 / 127.0;   // 2/(H+1)
constexpr double dDX2 = dDX * dDX;
constexpr double dDY2 = dDY * dDY;
constexpr double dDEN = 2.0 * (dDX2 + dDY2);

#define F_DX2  ((float)dDX2)
#define F_DY2  ((float)dDY2)
#define F_IDEN ((float)(1.0 / dDEN))
#define F_CB   ((float)(dDX2 * dDY2 / dDEN))
#define F_I2DX ((float)(1.0 / (2.0 * dDX)))
#define F_I2DY ((float)(1.0 / (2.0 * dDY)))
#define F_IDT  (10.0f)                       // 1/DT
#define F_DTDX ((float)(0.1 / dDX))          // DT/DX
#define F_DTDY ((float)(0.1 / dDY))          // DT/DY
#define F_PGX  ((float)(0.1 / (2.0 * dDX)))  // DT/(2*RHO*DX)
#define F_PGY  ((float)(0.1 / (2.0 * dDY)))  // DT/(2*RHO*DY)
#define F_NUX  ((float)(0.01 / dDX2))        // NU*DT/DX2
#define F_NUY  ((float)(0.01 / dDY2))        // NU*DT/DY2
#define F_FDT  (0.1f)                        // FRC*DT

#define NPLANE_F  (128 * 128)        // floats per plane
#define NPLANE_F4 (NPLANE_F / 4)     // 4096 float4 per plane
#define NTOT_F    (256 * NPLANE_F)   // 4M floats per field array

// ---------------------------------------------------------------------------
// Device scratch (allocation-free)
// ---------------------------------------------------------------------------
__device__ float g_pT [NTOT_F];
__device__ float g_uT0[NTOT_F];
__device__ float g_vT0[NTOT_F];
__device__ float g_uA [NTOT_F];
__device__ float g_vA [NTOT_F];
__device__ float g_uB [NTOT_F];
__device__ float g_vB [NTOT_F];

// ---------------------------------------------------------------------------
// init_p: p[(b,d)][r][c] = sum_f xpad[b,r,c,f]*w[d,f] + b_lin[d]
// One block per (r, b). Borders (r/c = 0 or 127) = b_lin[d].
// ---------------------------------------------------------------------------
__global__ __launch_bounds__(256) void init_p(
    const float* __restrict__ x, const float* __restrict__ wm,
    const float* __restrict__ bl, float* __restrict__ pT)
{
    __shared__ float xs[128][65];
    __shared__ float ws[32][64];
    __shared__ float bls[32];

    int r = blockIdx.x, b = blockIdx.y;
    int tid = threadIdx.x;

    if (tid < 32) bls[tid] = bl[tid];
    for (int i = tid; i < 32 * 64; i += 256) ws[i >> 6][i & 63] = wm[i];

    bool border_r = (r == 0 || r == 127);
    if (!border_r) {
        for (int i = tid; i < 128 * 64; i += 256) {
            int c = i >> 6, f = i & 63;
            float val = 0.0f;
            if (c >= 1 && c <= 126)
                val = x[((b * 126 + (r - 1)) * 126 + (c - 1)) * 64 + f];
            xs[c][f] = val;
        }
    }
    __syncthreads();

    if (border_r) {
        for (int i = tid; i < 32 * 128; i += 256) {
            int d = i >> 7, c = i & 127;
            pT[((b * 32 + d) * 128 + r) * 128 + c] = bls[d];
        }
        return;
    }

    int cq = tid & 31;        // lane -> cells cq, cq+32, cq+64, cq+96
    int d0 = (tid >> 5) * 4;  // warp -> 4 d rows

    float acc[4][4] = {};
    for (int f = 0; f < 64; f++) {
        float w0 = ws[d0][f], w1 = ws[d0 + 1][f], w2 = ws[d0 + 2][f], w3 = ws[d0 + 3][f];
#pragma unroll
        for (int cj = 0; cj < 4; cj++) {
            float xv = xs[cq + 32 * cj][f];
            acc[0][cj] += w0 * xv; acc[1][cj] += w1 * xv;
            acc[2][cj] += w2 * xv; acc[3][cj] += w3 * xv;
        }
    }
#pragma unroll
    for (int di = 0; di < 4; di++) {
        int d = d0 + di;
        float blv = bls[d];
#pragma unroll
        for (int cj = 0; cj < 4; cj++)
            pT[((b * 32 + d) * 128 + r) * 128 + (cq + 32 * cj)] = acc[di][cj] + blv;
    }
}

// ---------------------------------------------------------------------------
// transpose u0/v0: [b][r][c][d] -> plane-major [(b*32+d)][r][c]
// One block per (r, b, field).
// ---------------------------------------------------------------------------
__global__ __launch_bounds__(256) void transpose_uv(
    const float* __restrict__ u0, const float* __restrict__ v0,
    float* __restrict__ uT, float* __restrict__ vT)
{
    __shared__ float t[128][33];
    int r = blockIdx.x, b = blockIdx.y;
    const float* src = (blockIdx.z == 0) ? u0 : v0;
    float*       dst = (blockIdx.z == 0) ? uT : vT;

    for (int i = threadIdx.x; i < 4096; i += 256) {
        int c = i >> 5, d = i & 31;
        t[c][d] = src[((b * 128 + r) * 128 + c) * 32 + d];
    }
    __syncthreads();
    for (int i = threadIdx.x; i < 4096; i += 256) {
        int d = i >> 7, c = i & 127;
        dst[((b * 32 + d) * 128 + r) * 128 + c] = t[c][d];
    }
}

// ---------------------------------------------------------------------------
// Fused simulation: 1 CTA = 1 (b,d) plane. 512 threads = 16 warps.
// Warp w owns rows r = 1+w, 1+w+16, ... (<=126). Lane l owns cells 4l..4l+3.
// smem: double-buffered p plane (2 x 64 KB). b-source lives in registers.
// E/W neighbors via lane shuffles (periodic wrap == lane wrap).
// ---------------------------------------------------------------------------
extern __shared__ float4 sm4[];   // 2 * 4096 float4 = 128 KB
#define SMP(buf, r, l) sm4[(buf) * NPLANE_F4 + (r) * 32 + (l)]

__device__ __forceinline__ float shflW(float v) {
    return __shfl_sync(0xffffffffu, v, (threadIdx.x + 31) & 31);
}
__device__ __forceinline__ float shflE(float v) {
    return __shfl_sync(0xffffffffu, v, (threadIdx.x + 1) & 31);
}

__global__ __launch_bounds__(512) void fused_sim(
    const float4* __restrict__ pT,
    const float4* __restrict__ uT0, const float4* __restrict__ vT0,
    float4* __restrict__ uA, float4* __restrict__ vA,
    float4* __restrict__ uB, float4* __restrict__ vB,
    float* __restrict__ out)
{
    int bd   = blockIdx.x;
    int tid  = threadIdx.x;
    int lane = tid & 31;
    int wid  = tid >> 5;
    int rbase = 1 + wid;

    // ---- load initial p plane into smem buffer 0 ----
    const float4* pP = pT + (size_t)bd * NPLANE_F4;
#pragma unroll
    for (int k = 0; k < 8; k++)
        sm4[tid + k * 512] = pP[tid + k * 512];
    __syncthreads();

    float4 pown[8];
    float4 bown[8];
#pragma unroll
    for (int j = 0; j < 8; j++) {
        int r = rbase + 16 * j;
        if (r <= 126) pown[j] = SMP(0, r, lane);
    }

    const float4* uc_ = uT0 + (size_t)bd * NPLANE_F4;
    const float4* vc_ = vT0 + (size_t)bd * NPLANE_F4;

    for (int it = 0; it < 3; it++) {
        // ---------------- build_b -> registers ----------------
#pragma unroll
        for (int j = 0; j < 8; j++) {
            int r = rbase + 16 * j;
            if (r > 126) continue;
            float4 uo = __ldg(uc_ + r * 32 + lane);
            float4 un = __ldg(uc_ + (r - 1) * 32 + lane);
            float4 us = __ldg(uc_ + (r + 1) * 32 + lane);
            float4 vo = __ldg(vc_ + r * 32 + lane);
            float4 vn = __ldg(vc_ + (r - 1) * 32 + lane);
            float4 vs = __ldg(vc_ + (r + 1) * 32 + lane);
            float uw0 = shflW(uo.w), ue3 = shflE(uo.x);
            float vw0 = shflW(vo.w), ve3 = shflE(vo.x);
            float4 bv;
#define BQ(q, UW, UE, VW, VE) { \
            float dudx = (UE - UW) * F_I2DX; \
            float dvdy = (vs.q - vn.q) * F_I2DY; \
            float dudy = (us.q - un.q) * F_I2DY; \
            float dvdx = (VE - VW) * F_I2DX; \
            bv.q = (dudx + dvdy) * F_IDT - dudx * dudx \
                 - 2.0f * dudy * dvdx - dvdy * dvdy; }
            BQ(x, uw0,  uo.y, vw0,  vo.y)
            BQ(y, uo.x, uo.z, vo.x, vo.z)
            BQ(z, uo.y, uo.w, vo.y, vo.w)
            BQ(w, uo.z, ue3,  vo.z, ve3)
#undef BQ
            bown[j] = bv;
        }

        // ---------------- 20 Jacobi sweeps in smem ----------------
        int cur = 0;
        for (int s = 0; s < 20; s++) {
#pragma unroll
            for (int j = 0; j < 8; j++) {
                int r = rbase + 16 * j;
                if (r > 126) continue;
                float4 N = SMP(cur, r - 1, lane);
                float4 S = SMP(cur, r + 1, lane);
                float4 po = pown[j];
                float w0 = shflW(po.w), e3 = shflE(po.x);
                float4 bv = bown[j];
                float4 o;
                o.x = ((po.y + w0)   * F_DY2 + (N.x + S.x) * F_DX2) * F_IDEN - F_CB * bv.x;
                o.y = ((po.z + po.x) * F_DY2 + (N.y + S.y) * F_DX2) * F_IDEN - F_CB * bv.y;
                o.z = ((po.w + po.y) * F_DY2 + (N.z + S.z) * F_DX2) * F_IDEN - F_CB * bv.z;
                o.w = ((e3   + po.z) * F_DY2 + (N.w + S.w) * F_DX2) * F_IDEN - F_CB * bv.w;
                SMP(cur ^ 1, r, lane) = o;
                if (r == 1)   SMP(cur ^ 1, 0,   lane) = o;
                if (r == 126) SMP(cur ^ 1, 127, lane) = o;
                pown[j] = o;
            }
            __syncthreads();
            cur ^= 1;
        }
        // 20 sweeps (even) -> current p is in buffer 0 and in pown.

        // ---------------- velocity (iters 0,1 only; iter 2's is dead) ----
        if (it < 2) {
            float4* uoG = ((it == 0) ? uA : uB) + (size_t)bd * NPLANE_F4;
            float4* voG = ((it == 0) ? vA : vB) + (size_t)bd * NPLANE_F4;
#pragma unroll
            for (int j = 0; j < 8; j++) {
                int r = rbase + 16 * j;
                if (r > 126) continue;
                float4 uo = __ldg(uc_ + r * 32 + lane);
                float4 un = __ldg(uc_ + (r - 1) * 32 + lane);
                float4 us = __ldg(uc_ + (r + 1) * 32 + lane);
                float4 vo = __ldg(vc_ + r * 32 + lane);
                float4 vn = __ldg(vc_ + (r - 1) * 32 + lane);
                float4 vs = __ldg(vc_ + (r + 1) * 32 + lane);
                float4 pN = SMP(0, r - 1, lane);
                float4 pS = SMP(0, r + 1, lane);
                float4 po = pown[j];
                float uw0 = shflW(uo.w), ue3 = shflE(uo.x);
                float vw0 = shflW(vo.w), ve3 = shflE(vo.x);
                float pw0 = shflW(po.w), pe3 = shflE(po.x);
                float4 ru, rv;
#define VQ(q, UW, UE, VW, VE, PW, PE) { \
                float uc = uo.q, vc = vo.q; \
                ru.q = uc - uc * F_DTDX * (uc - UW) - vc * F_DTDY * (uc - un.q) \
                     - F_PGX * (PE - PW) \
                     + F_NUX * (UE - 2.0f * uc + UW) + F_NUY * (us.q - 2.0f * uc + un.q) \
                     + F_FDT; \
                rv.q = vc - uc * F_DTDX * (vc - VW) - vc * F_DTDY * (vc - vn.q) \
                     - F_PGY * (pS.q - pN.q) \
                     + F_NUX * (VE - 2.0f * vc + VW) + F_NUY * (vs.q - 2.0f * vc + vn.q); }
                VQ(x, uw0,  uo.y, vw0,  vo.y, pw0,  po.y)
                VQ(y, uo.x, uo.z, vo.x, vo.z, po.x, po.z)
                VQ(z, uo.y, uo.w, vo.y, vo.w, po.y, po.w)
                VQ(w, uo.z, ue3,  vo.z, ve3,  po.z, pe3)
#undef VQ
                uoG[r * 32 + lane] = ru;
                voG[r * 32 + lane] = rv;
            }
            float4 z = make_float4(0.f, 0.f, 0.f, 0.f);
            if (wid == 14) { uoG[lane] = z;            voG[lane] = z; }
            if (wid == 15) { uoG[127 * 32 + lane] = z; voG[127 * 32 + lane] = z; }
            __syncthreads();   // global u,v writes visible block-wide for next build_b
            uc_ = uoG;
            vc_ = voG;
        }
    }

    // ---- output: out[b][c][d] = p[row 127][c] ----
    if (tid < 128) {
        const float* smf = (const float*)sm4;   // buffer 0
        float val = smf[127 * 128 + tid];
        int b = bd >> 5, d = bd & 31;
        out[(b * 128 + tid) * 32 + d] = val;
    }
}

// ---------------------------------------------------------------------------
// Host driver
// ---------------------------------------------------------------------------
extern "C" void kernel_launch(void* const* d_in, const int* in_sizes, int n_in,
                              void* d_out, int out_size)
{
    const float* x    = (const float*)d_in[0];
    const float* u0   = (const float*)d_in[1];
    const float* v0   = (const float*)d_in[2];
    const float* wm   = (const float*)d_in[3];
    const float* blin = (const float*)d_in[4];

    float *pT, *uT0, *vT0, *uA, *vA, *uB, *vB;
    cudaGetSymbolAddress((void**)&pT,  g_pT);
    cudaGetSymbolAddress((void**)&uT0, g_uT0);
    cudaGetSymbolAddress((void**)&vT0, g_vT0);
    cudaGetSymbolAddress((void**)&uA,  g_uA);
    cudaGetSymbolAddress((void**)&vA,  g_vA);
    cudaGetSymbolAddress((void**)&uB,  g_uB);
    cudaGetSymbolAddress((void**)&vB,  g_vB);

    cudaFuncSetAttribute(fused_sim, cudaFuncAttributeMaxDynamicSharedMemorySize,
                         2 * NPLANE_F * (int)sizeof(float));

    init_p<<<dim3(128, 8), 256>>>(x, wm, blin, pT);
    transpose_uv<<<dim3(128, 8, 2), 256>>>(u0, v0, uT0, vT0);

    fused_sim<<<256, 512, 2 * NPLANE_F * sizeof(float)>>>(
        (const float4*)pT, (const float4*)uT0, (const float4*)vT0,
        (float4*)uA, (float4*)vA, (float4*)uB, (float4*)vB,
        (float*)d_out);
}

// round 3
// speedup vs baseline: 3.5254x; 1.1797x over previous
#include <cuda_runtime.h>

// ---------------------------------------------------------------------------
// Problem: B=8, H=126, W=126, F=64, D=32; grids padded 128x128.
// Plane-major layout: field[(b*32+d)][r][c]; 256 independent planes.
// ---------------------------------------------------------------------------
constexpr double dDX  = 2.0 / 9.0;
constexpr double dDY  = 2.0 / 127.0;
constexpr double dDX2 = dDX * dDX;
constexpr double dDY2 = dDY * dDY;
constexpr double dDEN = 2.0 * (dDX2 + dDY2);

#define F_A    ((float)(dDY2 / dDEN))        // coeff for E/W
#define F_B    ((float)(dDX2 / dDEN))        // coeff for N/S
#define F_CB   ((float)(dDX2 * dDY2 / dDEN))
#define F_I2DX ((float)(1.0 / (2.0 * dDX)))
#define F_I2DY ((float)(1.0 / (2.0 * dDY)))
#define F_IDT  (10.0f)
#define F_DTDX ((float)(0.1 / dDX))
#define F_DTDY ((float)(0.1 / dDY))
#define F_PGX  ((float)(0.1 / (2.0 * dDX)))
#define F_PGY  ((float)(0.1 / (2.0 * dDY)))
#define F_NUX  ((float)(0.01 / dDX2))
#define F_NUY  ((float)(0.01 / dDY2))
#define F_FDT  (0.1f)

#define NPLANE_F  (128 * 128)
#define NPLANE_F4 (NPLANE_F / 4)
#define NTOT_F    (256 * NPLANE_F)

__device__ float g_pT [NTOT_F];
__device__ float g_uT0[NTOT_F];
__device__ float g_vT0[NTOT_F];
__device__ float g_uA [NTOT_F];
__device__ float g_vA [NTOT_F];
__device__ float g_uB [NTOT_F];
__device__ float g_vB [NTOT_F];

// ---------------------------------------------------------------------------
// Packed f32x2 helpers
// ---------------------------------------------------------------------------
__device__ __forceinline__ unsigned long long pk2(float lo, float hi) {
    unsigned long long r;
    asm("mov.b64 %0, {%1, %2};" : "=l"(r) : "f"(lo), "f"(hi));
    return r;
}
__device__ __forceinline__ void fma2(unsigned long long& acc,
                                     unsigned long long a, unsigned long long b) {
    asm("fma.rn.f32x2 %0, %1, %2, %0;" : "+l"(acc) : "l"(a), "l"(b));
}
__device__ __forceinline__ float lo32(unsigned long long v) {
    return __uint_as_float((unsigned)v);
}
__device__ __forceinline__ float hi32(unsigned long long v) {
    return __uint_as_float((unsigned)(v >> 32));
}

// ---------------------------------------------------------------------------
// init_p: p[(b,d)][r][c] = sum_f xpad[b,r,c,f]*w[d,f] + b_lin[d]
// Block per (r,b). 256 thr: warp wz owns d=4wz..4wz+3 (2 packed d-pairs),
// lane owns cells lane+32j. x tile in smem [c][f] padded to 68 floats.
// ---------------------------------------------------------------------------
__global__ __launch_bounds__(256) void init_p(
    const float* __restrict__ x, const float* __restrict__ wm,
    const float* __restrict__ bl, float* __restrict__ pT)
{
    __shared__ __align__(16) float  xs[128][68];   // 34.8 KB
    __shared__ __align__(16) float2 wsp[16][64];   // 8 KB: wsp[dp][f]=(w[2dp][f],w[2dp+1][f])
    __shared__ float bls[32];

    int r = blockIdx.x, b = blockIdx.y;
    int tid = threadIdx.x;

    if (tid < 32) bls[tid] = bl[tid];
    for (int i = tid; i < 16 * 64; i += 256) {
        int dp = i >> 6, f = i & 63;
        wsp[dp][f] = make_float2(wm[(2 * dp) * 64 + f], wm[(2 * dp + 1) * 64 + f]);
    }

    bool border_r = (r == 0 || r == 127);
    if (!border_r) {
        for (int i = tid; i < 128 * 64; i += 256) {
            int c = i >> 6, f = i & 63;
            float val = 0.0f;
            if (c >= 1 && c <= 126)
                val = x[((b * 126 + (r - 1)) * 126 + (c - 1)) * 64 + f];
            xs[c][f] = val;
        }
    }
    __syncthreads();

    if (border_r) {
        for (int i = tid; i < 32 * 128; i += 256) {
            int d = i >> 7, c = i & 127;
            pT[((b * 32 + d) * 128 + r) * 128 + c] = bls[d];
        }
        return;
    }

    int lane = tid & 31;
    int wz   = tid >> 5;            // 0..7
    int dp0  = 2 * wz;              // d-pairs dp0, dp0+1  -> d = 4wz..4wz+3

    unsigned long long acc[2][4];
#pragma unroll
    for (int dp = 0; dp < 2; dp++)
#pragma unroll
        for (int j = 0; j < 4; j++) acc[dp][j] = 0ULL;

#pragma unroll 4
    for (int fc = 0; fc < 16; fc++) {
        // x: 4 cells x 4 f values (float4 over f)
        float4 xv[4];
#pragma unroll
        for (int j = 0; j < 4; j++)
            xv[j] = reinterpret_cast<const float4*>(&xs[lane + 32 * j][0])[fc];

        // w pairs for f=4fc..4fc+3, both d-pairs (LDS.128 broadcast)
        ulonglong2 wA0 = *reinterpret_cast<const ulonglong2*>(&wsp[dp0][4 * fc]);
        ulonglong2 wB0 = *reinterpret_cast<const ulonglong2*>(&wsp[dp0][4 * fc + 2]);
        ulonglong2 wA1 = *reinterpret_cast<const ulonglong2*>(&wsp[dp0 + 1][4 * fc]);
        ulonglong2 wB1 = *reinterpret_cast<const ulonglong2*>(&wsp[dp0 + 1][4 * fc + 2]);
        unsigned long long w0[4] = { wA0.x, wA0.y, wB0.x, wB0.y };
        unsigned long long w1[4] = { wA1.x, wA1.y, wB1.x, wB1.y };

#pragma unroll
        for (int j = 0; j < 4; j++) {
            const float* xvf = reinterpret_cast<const float*>(&xv[j]);
#pragma unroll
            for (int k = 0; k < 4; k++) {
                unsigned long long xx = pk2(xvf[k], xvf[k]);
                fma2(acc[0][j], xx, w0[k]);
                fma2(acc[1][j], xx, w1[k]);
            }
        }
    }

#pragma unroll
    for (int dp = 0; dp < 2; dp++) {
        int d = 4 * wz + 2 * dp;
        float bl0 = bls[d], bl1 = bls[d + 1];
#pragma unroll
        for (int j = 0; j < 4; j++) {
            int c = lane + 32 * j;
            pT[((b * 32 + d)     * 128 + r) * 128 + c] = lo32(acc[dp][j]) + bl0;
            pT[((b * 32 + d + 1) * 128 + r) * 128 + c] = hi32(acc[dp][j]) + bl1;
        }
    }
}

// ---------------------------------------------------------------------------
// transpose u0/v0: [b][r][c][d] -> [(b*32+d)][r][c]
// ---------------------------------------------------------------------------
__global__ __launch_bounds__(256) void transpose_uv(
    const float* __restrict__ u0, const float* __restrict__ v0,
    float* __restrict__ uT, float* __restrict__ vT)
{
    __shared__ float t[128][33];
    int r = blockIdx.x, b = blockIdx.y;
    const float* src = (blockIdx.z == 0) ? u0 : v0;
    float*       dst = (blockIdx.z == 0) ? uT : vT;

    for (int i = threadIdx.x; i < 4096; i += 256) {
        int c = i >> 5, d = i & 31;
        t[c][d] = src[((b * 128 + r) * 128 + c) * 32 + d];
    }
    __syncthreads();
    for (int i = threadIdx.x; i < 4096; i += 256) {
        int d = i >> 7, c = i & 127;
        dst[((b * 32 + d) * 128 + r) * 128 + c] = t[c][d];
    }
}

// ---------------------------------------------------------------------------
// Fused sim: 1 CTA = 1 plane. 512 thr = 16 warps; warp w owns rows 8w..8w+7,
// lane owns cols 4l..4l+3. p + (-CB*b) live in registers; only 2 boundary
// rows per warp exchanged per sweep via a 32 KB double-buffered smem halo.
// ---------------------------------------------------------------------------
__device__ __forceinline__ float shflW(float v) {
    return __shfl_sync(0xffffffffu, v, (threadIdx.x + 31) & 31);
}
__device__ __forceinline__ float shflE(float v) {
    return __shfl_sync(0xffffffffu, v, (threadIdx.x + 1) & 31);
}

__global__ __launch_bounds__(512) void fused_sim(
    const float4* __restrict__ pT,
    const float4* __restrict__ uT0, const float4* __restrict__ vT0,
    float4* __restrict__ uA, float4* __restrict__ vA,
    float4* __restrict__ uB, float4* __restrict__ vB,
    float* __restrict__ out)
{
    __shared__ float4 halo[2][16][2][32];   // [buf][warp][top/bot][lane] 32 KB

    int bd   = blockIdx.x;
    int tid  = threadIdx.x;
    int lane = tid & 31;
    int wid  = tid >> 5;
    int r0   = wid << 3;                    // first owned row

    const float4* pP = pT + (size_t)bd * NPLANE_F4;
    float4 P[8];
#pragma unroll
    for (int i = 0; i < 8; i++) P[i] = pP[(r0 + i) * 32 + lane];

    float4 C[8];                            // -CB * b per owned row

    const float4* uc_ = uT0 + (size_t)bd * NPLANE_F4;
    const float4* vc_ = vT0 + (size_t)bd * NPLANE_F4;

    for (int it = 0; it < 3; it++) {
        // ---------------- build_b -> C registers ----------------
#pragma unroll
        for (int i = 0; i < 8; i++) {
            int r = r0 + i;
            if (r < 1 || r > 126) continue;
            float4 uo = __ldg(uc_ + r * 32 + lane);
            float4 un = __ldg(uc_ + (r - 1) * 32 + lane);
            float4 us = __ldg(uc_ + (r + 1) * 32 + lane);
            float4 vo = __ldg(vc_ + r * 32 + lane);
            float4 vn = __ldg(vc_ + (r - 1) * 32 + lane);
            float4 vs = __ldg(vc_ + (r + 1) * 32 + lane);
            float uw0 = shflW(uo.w), ue3 = shflE(uo.x);
            float vw0 = shflW(vo.w), ve3 = shflE(vo.x);
            float4 cv;
#define BQ(q, UW, UE, VW, VE) { \
            float dudx = (UE - UW) * F_I2DX; \
            float dvdy = (vs.q - vn.q) * F_I2DY; \
            float dudy = (us.q - un.q) * F_I2DY; \
            float dvdx = (VE - VW) * F_I2DX; \
            float bv = (dudx + dvdy) * F_IDT - dudx * dudx \
                     - 2.0f * dudy * dvdx - dvdy * dvdy; \
            cv.q = -F_CB * bv; }
            BQ(x, uw0,  uo.y, vw0,  vo.y)
            BQ(y, uo.x, uo.z, vo.x, vo.z)
            BQ(z, uo.y, uo.w, vo.y, vo.w)
            BQ(w, uo.z, ue3,  vo.z, ve3)
#undef BQ
            C[i] = cv;
        }

        // ---------------- 20 Jacobi sweeps ----------------
        int pb = 0;
        for (int s = 0; s < 20; s++) {
            halo[pb][wid][0][lane] = P[0];
            halo[pb][wid][1][lane] = P[7];
            __syncthreads();
            float4 hN = (wid > 0)  ? halo[pb][wid - 1][1][lane] : P[0];
            float4 hS = (wid < 15) ? halo[pb][wid + 1][0][lane] : P[7];

            float4 oldN = hN;
#pragma unroll
            for (int i = 0; i < 8; i++) {
                int r = r0 + i;
                float4 cur = P[i];
                if (r >= 1 && r <= 126) {
                    float4 S = (i < 7) ? P[i + 1] : hS;
                    float w0 = shflW(cur.w), e3 = shflE(cur.x);
                    float4 o;
#define JC(q, Eo, Wo) \
                    o.q = __fmaf_rn(Eo, F_A, __fmaf_rn(Wo, F_A, \
                          __fmaf_rn(oldN.q, F_B, __fmaf_rn(S.q, F_B, C[i].q))));
                    JC(x, cur.y, w0)
                    JC(y, cur.z, cur.x)
                    JC(z, cur.w, cur.y)
                    JC(w, e3,    cur.z)
#undef JC
                    P[i] = o;
                }
                oldN = cur;
            }
            if (wid == 0)  P[0] = P[1];
            if (wid == 15) P[7] = P[6];
            pb ^= 1;
        }

        // ---------------- velocity (it 0,1; it 2's result is dead) ------
        if (it < 2) {
            // exchange final-p boundary rows
            halo[0][wid][0][lane] = P[0];
            halo[0][wid][1][lane] = P[7];
            __syncthreads();
            float4 hN = (wid > 0)  ? halo[0][wid - 1][1][lane] : P[0];
            float4 hS = (wid < 15) ? halo[0][wid + 1][0][lane] : P[7];

            float4* uoG = ((it == 0) ? uA : uB) + (size_t)bd * NPLANE_F4;
            float4* voG = ((it == 0) ? vA : vB) + (size_t)bd * NPLANE_F4;
            float4 z4 = make_float4(0.f, 0.f, 0.f, 0.f);

#pragma unroll
            for (int i = 0; i < 8; i++) {
                int r = r0 + i;
                if (r < 1 || r > 126) {
                    uoG[r * 32 + lane] = z4;
                    voG[r * 32 + lane] = z4;
                    continue;
                }
                float4 uo = __ldg(uc_ + r * 32 + lane);
                float4 un = __ldg(uc_ + (r - 1) * 32 + lane);
                float4 us = __ldg(uc_ + (r + 1) * 32 + lane);
                float4 vo = __ldg(vc_ + r * 32 + lane);
                float4 vn = __ldg(vc_ + (r - 1) * 32 + lane);
                float4 vs = __ldg(vc_ + (r + 1) * 32 + lane);
                float4 pN = (i > 0) ? P[i - 1] : hN;
                float4 pS = (i < 7) ? P[i + 1] : hS;
                float4 po = P[i];
                float uw0 = shflW(uo.w), ue3 = shflE(uo.x);
                float vw0 = shflW(vo.w), ve3 = shflE(vo.x);
                float pw0 = shflW(po.w), pe3 = shflE(po.x);
                float4 ru, rv;
#define VQ(q, UW, UE, VW, VE, PW, PE) { \
                float uc = uo.q, vc = vo.q; \
                ru.q = uc - uc * F_DTDX * (uc - UW) - vc * F_DTDY * (uc - un.q) \
                     - F_PGX * (PE - PW) \
                     + F_NUX * (UE - 2.0f * uc + UW) + F_NUY * (us.q - 2.0f * uc + un.q) \
                     + F_FDT; \
                rv.q = vc - uc * F_DTDX * (vc - VW) - vc * F_DTDY * (vc - vn.q) \
                     - F_PGY * (pS.q - pN.q) \
                     + F_NUX * (VE - 2.0f * vc + VW) + F_NUY * (vs.q - 2.0f * vc + vn.q); }
                VQ(x, uw0,  uo.y, vw0,  vo.y, pw0,  po.y)
                VQ(y, uo.x, uo.z, vo.x, vo.z, po.x, po.z)
                VQ(z, uo.y, uo.w, vo.y, vo.w, po.y, po.w)
                VQ(w, uo.z, ue3,  vo.z, ve3,  po.z, pe3)
#undef VQ
                uoG[r * 32 + lane] = ru;
                voG[r * 32 + lane] = rv;
            }
            __syncthreads();   // make u,v global writes visible block-wide
            uc_ = uoG;
            vc_ = voG;
        }
    }

    // ---- output: out[(b*128 + c)*32 + d] = p[row 127][c] ----
    if (wid == 15) {
        int b = bd >> 5, d = bd & 31;
        int cb = lane << 2;
        out[((b << 7) + cb + 0) * 32 + d] = P[7].x;
        out[((b << 7) + cb + 1) * 32 + d] = P[7].y;
        out[((b << 7) + cb + 2) * 32 + d] = P[7].z;
        out[((b << 7) + cb + 3) * 32 + d] = P[7].w;
    }
}

// ---------------------------------------------------------------------------
// Host driver
// ---------------------------------------------------------------------------
extern "C" void kernel_launch(void* const* d_in, const int* in_sizes, int n_in,
                              void* d_out, int out_size)
{
    const float* x    = (const float*)d_in[0];
    const float* u0   = (const float*)d_in[1];
    const float* v0   = (const float*)d_in[2];
    const float* wm   = (const float*)d_in[3];
    const float* blin = (const float*)d_in[4];

    float *pT, *uT0, *vT0, *uA, *vA, *uB, *vB;
    cudaGetSymbolAddress((void**)&pT,  g_pT);
    cudaGetSymbolAddress((void**)&uT0, g_uT0);
    cudaGetSymbolAddress((void**)&vT0, g_vT0);
    cudaGetSymbolAddress((void**)&uA,  g_uA);
    cudaGetSymbolAddress((void**)&vA,  g_vA);
    cudaGetSymbolAddress((void**)&uB,  g_uB);
    cudaGetSymbolAddress((void**)&vB,  g_vB);

    init_p<<<dim3(128, 8), 256>>>(x, wm, blin, pT);
    transpose_uv<<<dim3(128, 8, 2), 256>>>(u0, v0, uT0, vT0);

    fused_sim<<<256, 512>>>(
        (const float4*)pT, (const float4*)uT0, (const float4*)vT0,
        (float4*)uA, (float4*)vA, (float4*)uB, (float4*)vB,
        (float*)d_out);
}